// round 2
// baseline (speedup 1.0000x reference)
#include <cuda_runtime.h>
#include <cstdint>

namespace {

constexpr int Bv = 2, Hv = 16, Sv = 2048, Dv = 64;
constexpr int BM = 64;   // query rows per CTA
constexpr int BN = 32;   // kv rows per tile
constexpr int QS = 72;   // smem row stride (floats) for Q/K/V -> conflict-free frags
constexpr int PS = 36;   // smem row stride for mask/P buffer
constexpr float SCALE = 0.125f;  // 1/sqrt(64)

__device__ __forceinline__ uint32_t f2tf(float f) {
    uint32_t r;
    asm("cvt.rna.tf32.f32 %0, %1;" : "=r"(r) : "f"(f));
    return r;
}

__device__ __forceinline__ void mma8(float* c, const uint32_t* a, const uint32_t* b) {
    asm volatile(
        "mma.sync.aligned.m16n8k8.row.col.f32.tf32.tf32.f32 "
        "{%0,%1,%2,%3}, {%4,%5,%6,%7}, {%8,%9}, {%0,%1,%2,%3};"
        : "+f"(c[0]), "+f"(c[1]), "+f"(c[2]), "+f"(c[3])
        : "r"(a[0]), "r"(a[1]), "r"(a[2]), "r"(a[3]), "r"(b[0]), "r"(b[1]));
}

__global__ void __launch_bounds__(128)
attn_kernel(const float* __restrict__ q, const float* __restrict__ k,
            const float* __restrict__ v, const int* __restrict__ mask,
            float* __restrict__ out) {
    __shared__ float sQ[BM * QS];
    __shared__ float sK[BN * QS];
    __shared__ float sV[BN * QS];
    __shared__ float sPM[BM * PS];  // mask bits, then reused for P staging

    const int tid = threadIdx.x;
    const int warp = tid >> 5;
    const int lane = tid & 31;
    const int g = lane >> 2;    // groupID (row within 8)
    const int t = lane & 3;     // threadID_in_group
    const int r0 = warp * 16 + g;
    const int r1 = r0 + 8;

    const int bh = blockIdx.y;       // 0..31 (b*H + h)
    const int b  = bh >> 4;          // H = 16
    const int q0 = blockIdx.x * BM;

    const float* qg = q + ((size_t)bh * Sv + q0) * Dv;
    const float* kg = k + (size_t)bh * Sv * Dv;
    const float* vg = v + (size_t)bh * Sv * Dv;
    const int*   mg = mask + ((size_t)b * Sv + q0) * Sv;
    float*       og = out + ((size_t)bh * Sv + q0) * Dv;

    // ---- Load Q tile once: 64 x 64 f32, coalesced float4 ----
    for (int i = tid; i < BM * 16; i += 128) {
        int row = i >> 4, c4 = i & 15;
        float4 val = *reinterpret_cast<const float4*>(qg + row * Dv + c4 * 4);
        float* d = &sQ[row * QS + c4 * 4];
        d[0] = val.x; d[1] = val.y; d[2] = val.z; d[3] = val.w;
    }

    float o[8][4];
#pragma unroll
    for (int i = 0; i < 8; i++)
#pragma unroll
        for (int j = 0; j < 4; j++) o[i][j] = 0.f;
    float m0 = -1e30f, m1 = -1e30f, l0 = 0.f, l1 = 0.f;

    for (int kt = 0; kt < Sv / BN; kt++) {
        __syncthreads();  // protect sK/sV/sPM before overwrite
        const int kbase = kt * BN;

        // K/V tile loads: 32 x 64 f32 each, coalesced
        for (int i = tid; i < BN * 16; i += 128) {
            int row = i >> 4, c4 = i & 15;
            float4 kv4 = *reinterpret_cast<const float4*>(kg + (size_t)(kbase + row) * Dv + c4 * 4);
            float* dk = &sK[row * QS + c4 * 4];
            dk[0] = kv4.x; dk[1] = kv4.y; dk[2] = kv4.z; dk[3] = kv4.w;
            float4 vv4 = *reinterpret_cast<const float4*>(vg + (size_t)(kbase + row) * Dv + c4 * 4);
            float* dv = &sV[row * QS + c4 * 4];
            dv[0] = vv4.x; dv[1] = vv4.y; dv[2] = vv4.z; dv[3] = vv4.w;
        }
        // mask tile: 64 x 32 int32, store raw bits in float buffer
        for (int i = tid; i < BM * 8; i += 128) {
            int row = i >> 3, c4 = i & 7;
            int4 mi = *reinterpret_cast<const int4*>(mg + (size_t)row * Sv + kbase + c4 * 4);
            float* d = &sPM[row * PS + c4 * 4];
            d[0] = __int_as_float(mi.x); d[1] = __int_as_float(mi.y);
            d[2] = __int_as_float(mi.z); d[3] = __int_as_float(mi.w);
        }
        __syncthreads();

        // ---- S = Q @ K^T via 3xtf32 (hi/lo split => ~fp32 accuracy) ----
        float sacc[4][4];
#pragma unroll
        for (int nc = 0; nc < 4; nc++)
#pragma unroll
            for (int j = 0; j < 4; j++) sacc[nc][j] = 0.f;

#pragma unroll
        for (int kc = 0; kc < 8; kc++) {
            const int kk = kc * 8;
            float fa0 = sQ[r0 * QS + kk + t];
            float fa1 = sQ[r1 * QS + kk + t];
            float fa2 = sQ[r0 * QS + kk + t + 4];
            float fa3 = sQ[r1 * QS + kk + t + 4];
            uint32_t ah[4] = {f2tf(fa0), f2tf(fa1), f2tf(fa2), f2tf(fa3)};
            uint32_t al[4] = {f2tf(fa0 - __uint_as_float(ah[0])),
                              f2tf(fa1 - __uint_as_float(ah[1])),
                              f2tf(fa2 - __uint_as_float(ah[2])),
                              f2tf(fa3 - __uint_as_float(ah[3]))};
#pragma unroll
            for (int nc = 0; nc < 4; nc++) {
                float fb0 = sK[(nc * 8 + g) * QS + kk + t];
                float fb1 = sK[(nc * 8 + g) * QS + kk + t + 4];
                uint32_t bhv[2] = {f2tf(fb0), f2tf(fb1)};
                uint32_t blv[2] = {f2tf(fb0 - __uint_as_float(bhv[0])),
                                   f2tf(fb1 - __uint_as_float(bhv[1]))};
                mma8(sacc[nc], ah, bhv);
                mma8(sacc[nc], ah, blv);
                mma8(sacc[nc], al, bhv);
            }
        }

        // ---- mask + online softmax ----
        float mx0 = -1e30f, mx1 = -1e30f;
#pragma unroll
        for (int nc = 0; nc < 4; nc++) {
            int c0 = nc * 8 + 2 * t;
            int m00 = __float_as_int(sPM[r0 * PS + c0]);
            int m01 = __float_as_int(sPM[r0 * PS + c0 + 1]);
            int m10 = __float_as_int(sPM[r1 * PS + c0]);
            int m11 = __float_as_int(sPM[r1 * PS + c0 + 1]);
            sacc[nc][0] = m00 ? sacc[nc][0] * SCALE : -1e9f;
            sacc[nc][1] = m01 ? sacc[nc][1] * SCALE : -1e9f;
            sacc[nc][2] = m10 ? sacc[nc][2] * SCALE : -1e9f;
            sacc[nc][3] = m11 ? sacc[nc][3] * SCALE : -1e9f;
            mx0 = fmaxf(mx0, fmaxf(sacc[nc][0], sacc[nc][1]));
            mx1 = fmaxf(mx1, fmaxf(sacc[nc][2], sacc[nc][3]));
        }
        mx0 = fmaxf(mx0, __shfl_xor_sync(0xffffffffu, mx0, 1));
        mx0 = fmaxf(mx0, __shfl_xor_sync(0xffffffffu, mx0, 2));
        mx1 = fmaxf(mx1, __shfl_xor_sync(0xffffffffu, mx1, 1));
        mx1 = fmaxf(mx1, __shfl_xor_sync(0xffffffffu, mx1, 2));

        float m0n = fmaxf(m0, mx0), m1n = fmaxf(m1, mx1);
        float a0 = __expf(m0 - m0n), a1 = __expf(m1 - m1n);
        m0 = m0n; m1 = m1n;

        float rs0 = 0.f, rs1 = 0.f;
#pragma unroll
        for (int nc = 0; nc < 4; nc++) {
            int c0 = nc * 8 + 2 * t;
            float p00 = __expf(sacc[nc][0] - m0n);
            float p01 = __expf(sacc[nc][1] - m0n);
            float p10 = __expf(sacc[nc][2] - m1n);
            float p11 = __expf(sacc[nc][3] - m1n);
            rs0 += p00 + p01; rs1 += p10 + p11;
            sPM[r0 * PS + c0]     = p00;
            sPM[r0 * PS + c0 + 1] = p01;
            sPM[r1 * PS + c0]     = p10;
            sPM[r1 * PS + c0 + 1] = p11;
        }
        rs0 += __shfl_xor_sync(0xffffffffu, rs0, 1);
        rs0 += __shfl_xor_sync(0xffffffffu, rs0, 2);
        rs1 += __shfl_xor_sync(0xffffffffu, rs1, 1);
        rs1 += __shfl_xor_sync(0xffffffffu, rs1, 2);
        l0 = l0 * a0 + rs0;
        l1 = l1 * a1 + rs1;

#pragma unroll
        for (int nc = 0; nc < 8; nc++) {
            o[nc][0] *= a0; o[nc][1] *= a0;
            o[nc][2] *= a1; o[nc][3] *= a1;
        }
        __syncwarp();  // P staged to smem by own warp's lanes; make visible

        // ---- O += P @ V (plain tf32) ----
#pragma unroll
        for (int kc = 0; kc < 4; kc++) {
            const int kk = kc * 8;
            uint32_t pa[4] = {f2tf(sPM[r0 * PS + kk + t]),
                              f2tf(sPM[r1 * PS + kk + t]),
                              f2tf(sPM[r0 * PS + kk + t + 4]),
                              f2tf(sPM[r1 * PS + kk + t + 4])};
#pragma unroll
            for (int nc = 0; nc < 8; nc++) {
                uint32_t pb[2] = {f2tf(sV[(kk + t) * QS + nc * 8 + g]),
                                  f2tf(sV[(kk + t + 4) * QS + nc * 8 + g])};
                mma8(o[nc], pa, pb);
            }
        }
    }

    // ---- epilogue ----
    float inv0 = 1.f / l0, inv1 = 1.f / l1;
#pragma unroll
    for (int nc = 0; nc < 8; nc++) {
        int c0 = nc * 8 + 2 * t;
        float2 w0 = make_float2(o[nc][0] * inv0, o[nc][1] * inv0);
        float2 w1 = make_float2(o[nc][2] * inv1, o[nc][3] * inv1);
        *reinterpret_cast<float2*>(og + (size_t)r0 * Dv + c0) = w0;
        *reinterpret_cast<float2*>(og + (size_t)r1 * Dv + c0) = w1;
    }
}

}  // namespace

extern "C" void kernel_launch(void* const* d_in, const int* in_sizes, int n_in,
                              void* d_out, int out_size) {
    const float* q = (const float*)d_in[0];
    const float* k = (const float*)d_in[1];
    const float* v = (const float*)d_in[2];
    const int* mask = (const int*)d_in[3];
    float* out = (float*)d_out;

    dim3 grid(Sv / BM, Bv * Hv);  // (32, 32)
    dim3 block(128);
    attn_kernel<<<grid, block>>>(q, k, v, mask, out);
}